// round 5
// baseline (speedup 1.0000x reference)
#include <cuda_runtime.h>
#include <cuda_bf16.h>
#include <cstdint>

#define N_NODES 100000
#define N_EDGES 1600000
#define D 128
#define L_LAYERS 3

#define KPAD 272            // bf16 units per weight row (256 data + pad)
#define APAD 48             // bf16 units per A-tile row (32 data + pad)
#define TILE_M 64
#define N_TILES ((N_NODES + TILE_M - 1) / TILE_M)   // 1563
#define FUSED_GRID 148
#define FUSED_THREADS 384   // warps 0-3 GEMM, warps 4-11 aggregation

// ---------------- scratch (no allocations allowed) ----------------
__device__ int   g_deg[N_NODES];
__device__ float g_invdeg[N_NODES];
__device__ int   g_off[N_NODES + 1];
__device__ int   g_cursor[N_NODES];
__device__ int   g_csr[N_EDGES];
__device__ float g_h0[(size_t)N_NODES * D];
__device__ float g_h1[(size_t)N_NODES * D];
__device__ float g_hn[(size_t)N_NODES * D];
__device__ int   g_tileflag[N_TILES];

// ---------------- CSR build ----------------
__global__ void zero_deg_kernel() {
    int i = blockIdx.x * blockDim.x + threadIdx.x;
    if (i < N_NODES) g_deg[i] = 0;
}

__global__ void count_deg_kernel(const int* __restrict__ dst) {
    int e = blockIdx.x * blockDim.x + threadIdx.x;
    if (e < N_EDGES) atomicAdd(&g_deg[dst[e]], 1);
}

__global__ void scan_offsets_kernel() {
    __shared__ int warp_sums[32];
    __shared__ int carry_sh;
    int t = threadIdx.x, lane = t & 31, w = t >> 5;
    if (t == 0) carry_sh = 0;
    __syncthreads();
    for (int base = 0; base < N_NODES; base += 4096) {
        int i4 = base + t * 4;
        int4 v = make_int4(0, 0, 0, 0);
        if (i4 < N_NODES) v = *(const int4*)&g_deg[i4];
        int s0 = v.x, s1 = s0 + v.y, s2 = s1 + v.z, s3 = s2 + v.w;
        int incl = s3;
        #pragma unroll
        for (int off = 1; off < 32; off <<= 1) {
            int x = __shfl_up_sync(0xffffffffu, incl, off);
            if (lane >= off) incl += x;
        }
        if (lane == 31) warp_sums[w] = incl;
        __syncthreads();
        if (w == 0) {
            int s = warp_sums[lane];
            #pragma unroll
            for (int off = 1; off < 32; off <<= 1) {
                int x = __shfl_up_sync(0xffffffffu, s, off);
                if (lane >= off) s += x;
            }
            warp_sums[lane] = s;
        }
        __syncthreads();
        int carry = carry_sh;
        int woff = (w > 0) ? warp_sums[w - 1] : 0;
        int excl = carry + woff + incl - s3;
        if (i4 < N_NODES) {
            *(int4*)&g_off[i4] =
                make_int4(excl, excl + s0, excl + s1, excl + s2);
            *(float4*)&g_invdeg[i4] = make_float4(
                1.0f / (float)max(v.x, 1), 1.0f / (float)max(v.y, 1),
                1.0f / (float)max(v.z, 1), 1.0f / (float)max(v.w, 1));
            *(int4*)&g_cursor[i4] = make_int4(0, 0, 0, 0);
        }
        __syncthreads();
        if (t == 1023) carry_sh = carry + woff + incl;
        __syncthreads();
    }
    if (t == 0) g_off[N_NODES] = carry_sh;
}

__global__ void fill_csr_kernel(const int* __restrict__ src,
                                const int* __restrict__ dst) {
    int e = blockIdx.x * blockDim.x + threadIdx.x;
    if (e < N_EDGES) {
        int d = dst[e];
        int p = atomicAdd(&g_cursor[d], 1);
        g_csr[g_off[d] + p] = src[e];
    }
}

// ---------------- fused aggregation + bf16-split mma.sync GEMM ---------------
// out = relu([hin | mean-agg(hin)] @ [Ws;Wn] + bias)
// C = Ahi*Whi + Alo*Whi + Ahi*Wlo   (fp32 accum, m16n8k16 bf16 mma.sync)
//
// smem units (bf16): sWhi[128*KPAD] | sWlo[128*KPAD] | sA[2 bufs x (hi|lo)] | bias
#define SM_WHI 0
#define SM_WLO (128 * KPAD)                    // 34816
#define SM_A   (2 * 128 * KPAD)                // 69632
#define SM_ABUF (2 * TILE_M * APAD)            // 6144 units per buffer (hi|lo)
#define SM_BIAS (SM_A + 2 * SM_ABUF)           // 81920 units
#define FUSED_SMEM_BYTES ((SM_BIAS + 256) * 2) // 164352 B

__device__ __forceinline__ void mma_bf16(float c[4], uint32_t a0, uint32_t a1,
                                         uint32_t a2, uint32_t a3,
                                         uint32_t b0, uint32_t b1) {
    asm volatile(
        "mma.sync.aligned.m16n8k16.row.col.f32.bf16.bf16.f32 "
        "{%0,%1,%2,%3}, {%4,%5,%6,%7}, {%8,%9}, {%0,%1,%2,%3};"
        : "+f"(c[0]), "+f"(c[1]), "+f"(c[2]), "+f"(c[3])
        : "r"(a0), "r"(a1), "r"(a2), "r"(a3), "r"(b0), "r"(b1));
}

#define BAR_GEMM() asm volatile("bar.sync 1, 128;" ::: "memory")
#define BAR_AGG()  asm volatile("bar.sync 2, 256;" ::: "memory")

__global__ void __launch_bounds__(FUSED_THREADS, 1) sage_fused_kernel(
    const float* __restrict__ hin,
    const float* __restrict__ Ws, const float* __restrict__ Wn,
    const float* __restrict__ bias, float* __restrict__ out, int tag)
{
    extern __shared__ __align__(16) __nv_bfloat16 smem[];
    __nv_bfloat16* sWhi = smem + SM_WHI;
    __nv_bfloat16* sWlo = smem + SM_WLO;
    __nv_bfloat16* sA   = smem + SM_A;
    float* biasSm = (float*)(smem + SM_BIAS);

    int tid = threadIdx.x;
    int lane = tid & 31, warp = tid >> 5;

    // ---- prologue: split weights fp32 -> hi/lo bf16 permuted-K layout ----
    for (int idx = tid; idx < 128 * 256; idx += FUSED_THREADS) {
        int n = idx & 127;          // coalesced over n
        int k = idx >> 7;
        float w = (k < 128) ? __ldg(&Ws[k * 128 + n])
                            : __ldg(&Wn[(k - 128) * 128 + n]);
        __nv_bfloat16 hi = __float2bfloat16(w);
        __nv_bfloat16 lo = __float2bfloat16(w - __bfloat162float(hi));
        int group = k >> 4, l = k & 15;
        int p = ((l & 7) >> 1) * 4 + (l & 1) + ((l >> 3) << 1);
        int off = n * KPAD + group * 16 + p;
        sWhi[off] = hi;
        sWlo[off] = lo;
    }
    if (tid < 128) biasSm[tid] = __ldg(&bias[tid]);
    __syncthreads();

    float* hng = g_hn;

    if (tid < 128) {
        // ================= GEMM warps (0-3) =================
        int g = lane >> 2, tig = lane & 3;
        const int ptab[4] = {0, 8, 2, 10};

        for (int tile = blockIdx.x; tile < N_TILES; tile += gridDim.x) {
            int m0 = tile * TILE_M;

            float acc[16][4];
            #pragma unroll
            for (int nf = 0; nf < 16; nf++)
                #pragma unroll
                for (int r = 0; r < 4; r++) acc[nf][r] = 0.f;

            // prefetch chunk 0 (self, hin cols 0..31)
            float4 pref[4];
            #pragma unroll
            for (int i = 0; i < 4; i++) {
                int idx = tid + 128 * i;       // 512 float4
                int r = idx >> 3, c4 = idx & 7;
                int m = m0 + r;
                pref[i] = make_float4(0.f, 0.f, 0.f, 0.f);
                if (m < N_NODES)
                    pref[i] = *(const float4*)(hin + (size_t)m * D + c4 * 4);
            }

            #pragma unroll 1
            for (int kc = 0; kc < 8; kc++) {
                __nv_bfloat16* sAhi = sA + (kc & 1) * SM_ABUF;
                __nv_bfloat16* sAlo = sAhi + TILE_M * APAD;

                // convert prefetched fp32 -> hi/lo bf16 permuted-K smem
                #pragma unroll
                for (int i = 0; i < 4; i++) {
                    int idx = tid + 128 * i;
                    int r = idx >> 3, c4 = idx & 7;
                    float4 v = pref[i];
                    __nv_bfloat16 hx = __float2bfloat16(v.x);
                    __nv_bfloat16 hy = __float2bfloat16(v.y);
                    __nv_bfloat16 hz = __float2bfloat16(v.z);
                    __nv_bfloat16 hw = __float2bfloat16(v.w);
                    __nv_bfloat16 lx = __float2bfloat16(v.x - __bfloat162float(hx));
                    __nv_bfloat16 ly = __float2bfloat16(v.y - __bfloat162float(hy));
                    __nv_bfloat16 lz = __float2bfloat16(v.z - __bfloat162float(hz));
                    __nv_bfloat16 lw = __float2bfloat16(v.w - __bfloat162float(hw));
                    uint32_t hp0 = ((uint32_t)__bfloat16_as_ushort(hy) << 16) |
                                   __bfloat16_as_ushort(hx);
                    uint32_t hp1 = ((uint32_t)__bfloat16_as_ushort(hw) << 16) |
                                   __bfloat16_as_ushort(hz);
                    uint32_t lp0 = ((uint32_t)__bfloat16_as_ushort(ly) << 16) |
                                   __bfloat16_as_ushort(lx);
                    uint32_t lp1 = ((uint32_t)__bfloat16_as_ushort(lw) << 16) |
                                   __bfloat16_as_ushort(lz);
                    int group = c4 >> 2;
                    int p0 = ptab[c4 & 3];
                    int base = r * APAD + group * 16;
                    uint32_t* AH = (uint32_t*)sAhi;
                    uint32_t* AL = (uint32_t*)sAlo;
                    AH[(base + p0) >> 1]     = hp0;
                    AH[(base + p0 + 4) >> 1] = hp1;
                    AL[(base + p0) >> 1]     = lp0;
                    AL[(base + p0 + 4) >> 1] = lp1;
                }
                BAR_GEMM();

                // prefetch next chunk (wait for own CTA's aggregation
                // before touching neighbor data)
                if (kc < 7) {
                    int nkc = kc + 1;
                    if (nkc == 4) {
                        volatile int* f = &g_tileflag[tile];
                        while (*f != tag) {}
                        __threadfence_block();
                    }
                    const float* srcp = (nkc < 4) ? hin : hng;
                    int koff = (nkc & 3) * 32;
                    #pragma unroll
                    for (int i = 0; i < 4; i++) {
                        int idx = tid + 128 * i;
                        int r = idx >> 3, c4 = idx & 7;
                        int m = m0 + r;
                        pref[i] = make_float4(0.f, 0.f, 0.f, 0.f);
                        if (m < N_NODES)
                            pref[i] = *(const float4*)(srcp + (size_t)m * D +
                                                       koff + c4 * 4);
                    }
                }

                // mma over current buffer
                #pragma unroll
                for (int ks = 0; ks < 2; ks++) {
                    int ka = ks * 16;
                    int kw = kc * 32 + ks * 16;
                    int r0 = warp * 16;
                    uint2 t0 = *(const uint2*)&sAhi[(r0 + g) * APAD + ka + tig * 4];
                    uint2 t1 = *(const uint2*)&sAhi[(r0 + g + 8) * APAD + ka + tig * 4];
                    uint32_t Ah0 = t0.x, Ah1 = t1.x, Ah2 = t0.y, Ah3 = t1.y;
                    uint2 u0 = *(const uint2*)&sAlo[(r0 + g) * APAD + ka + tig * 4];
                    uint2 u1 = *(const uint2*)&sAlo[(r0 + g + 8) * APAD + ka + tig * 4];
                    uint32_t Al0 = u0.x, Al1 = u1.x, Al2 = u0.y, Al3 = u1.y;
                    #pragma unroll
                    for (int nf = 0; nf < 16; nf++) {
                        int nr = nf * 8 + g;
                        uint2 bh = *(const uint2*)&sWhi[nr * KPAD + kw + tig * 4];
                        uint2 bl = *(const uint2*)&sWlo[nr * KPAD + kw + tig * 4];
                        mma_bf16(acc[nf], Ah0, Ah1, Ah2, Ah3, bh.x, bh.y);
                        mma_bf16(acc[nf], Al0, Al1, Al2, Al3, bh.x, bh.y);
                        mma_bf16(acc[nf], Ah0, Ah1, Ah2, Ah3, bl.x, bl.y);
                    }
                }
            }

            // epilogue: + bias, relu, store
            int row0 = m0 + warp * 16 + g;
            #pragma unroll
            for (int nf = 0; nf < 16; nf++) {
                int col = nf * 8 + tig * 2;
                float bx = biasSm[col], by = biasSm[col + 1];
                if (row0 < N_NODES) {
                    float r0 = acc[nf][0] + bx; r0 = r0 > 0.f ? r0 : 0.f;
                    float r1 = acc[nf][1] + by; r1 = r1 > 0.f ? r1 : 0.f;
                    *(float2*)&out[(size_t)row0 * D + col] = make_float2(r0, r1);
                }
                if (row0 + 8 < N_NODES) {
                    float r2 = acc[nf][2] + bx; r2 = r2 > 0.f ? r2 : 0.f;
                    float r3 = acc[nf][3] + by; r3 = r3 > 0.f ? r3 : 0.f;
                    *(float2*)&out[(size_t)(row0 + 8) * D + col] = make_float2(r2, r3);
                }
            }
        }
    } else {
        // ================= aggregation warps (4-11) =================
        int aw = warp - 4;                     // 0..7
        const float4* H = (const float4*)hin;
        float4* HN = (float4*)hng;

        for (int tile = blockIdx.x; tile < N_TILES; tile += gridDim.x) {
            #pragma unroll 1
            for (int i = 0; i < 8; i++) {
                int node = tile * TILE_M + aw * 8 + i;
                if (node < N_NODES) {
                    int s = g_off[node], e = g_off[node + 1];
                    float4 a0 = make_float4(0.f, 0.f, 0.f, 0.f);
                    float4 a1 = a0, a2 = a0, a3 = a0;
                    int j = s;
                    for (; j + 4 <= e; j += 4) {
                        int u0 = __ldg(&g_csr[j]);
                        int u1 = __ldg(&g_csr[j + 1]);
                        int u2 = __ldg(&g_csr[j + 2]);
                        int u3 = __ldg(&g_csr[j + 3]);
                        float4 v0 = __ldg(&H[(size_t)u0 * 32 + lane]);
                        float4 v1 = __ldg(&H[(size_t)u1 * 32 + lane]);
                        float4 v2 = __ldg(&H[(size_t)u2 * 32 + lane]);
                        float4 v3 = __ldg(&H[(size_t)u3 * 32 + lane]);
                        a0.x += v0.x; a0.y += v0.y; a0.z += v0.z; a0.w += v0.w;
                        a1.x += v1.x; a1.y += v1.y; a1.z += v1.z; a1.w += v1.w;
                        a2.x += v2.x; a2.y += v2.y; a2.z += v2.z; a2.w += v2.w;
                        a3.x += v3.x; a3.y += v3.y; a3.z += v3.z; a3.w += v3.w;
                    }
                    for (; j < e; j++) {
                        int u = __ldg(&g_csr[j]);
                        float4 v = __ldg(&H[(size_t)u * 32 + lane]);
                        a0.x += v.x; a0.y += v.y; a0.z += v.z; a0.w += v.w;
                    }
                    float inv = g_invdeg[node];
                    float4 r;
                    r.x = (a0.x + a1.x + a2.x + a3.x) * inv;
                    r.y = (a0.y + a1.y + a2.y + a3.y) * inv;
                    r.z = (a0.z + a1.z + a2.z + a3.z) * inv;
                    r.w = (a0.w + a1.w + a2.w + a3.w) * inv;
                    HN[(size_t)node * 32 + lane] = r;
                }
            }
            __threadfence_block();
            BAR_AGG();
            if (warp == 4 && lane == 0)
                *(volatile int*)&g_tileflag[tile] = tag;
        }
    }
}

// ---------------- launch ----------------
extern "C" void kernel_launch(void* const* d_in, const int* in_sizes, int n_in,
                              void* d_out, int out_size)
{
    const float* x       = (const float*)d_in[0];
    const float* W_self  = (const float*)d_in[1];
    const float* W_neigh = (const float*)d_in[2];
    const float* bias    = (const float*)d_in[3];
    const int*   src     = (const int*)d_in[4];
    const int*   dst     = (const int*)d_in[5];
    float* out = (float*)d_out;

    void *p0, *p1;
    cudaGetSymbolAddress(&p0, g_h0);
    cudaGetSymbolAddress(&p1, g_h1);
    float* h0 = (float*)p0;
    float* h1 = (float*)p1;

    cudaFuncSetAttribute(sage_fused_kernel,
                         cudaFuncAttributeMaxDynamicSharedMemorySize,
                         FUSED_SMEM_BYTES);

    zero_deg_kernel<<<(N_NODES + 255) / 256, 256>>>();
    count_deg_kernel<<<(N_EDGES + 255) / 256, 256>>>(dst);
    scan_offsets_kernel<<<1, 1024>>>();
    fill_csr_kernel<<<(N_EDGES + 255) / 256, 256>>>(src, dst);

    const float* hin = x;
    float* houts[3] = {h0, h1, out};
    for (int l = 0; l < L_LAYERS; l++) {
        sage_fused_kernel<<<FUSED_GRID, FUSED_THREADS, FUSED_SMEM_BYTES>>>(
            hin, W_self + (size_t)l * D * D, W_neigh + (size_t)l * D * D,
            bias + (size_t)l * D, houts[l], l + 1);
        hin = houts[l];
    }
}

// round 6
// speedup vs baseline: 1.6080x; 1.6080x over previous
#include <cuda_runtime.h>
#include <cuda_bf16.h>
#include <cuda_fp16.h>
#include <cstdint>

#define N_NODES 100000
#define N_EDGES 1600000
#define D 128
#define L_LAYERS 3

#define KPAD 272            // bf16 units per weight row (256 data + pad)
#define APAD 48             // bf16 units per A-tile row (32 data + pad)
#define GEMM_TILES ((N_NODES + 127) / 128)   // 782
#define GEMM_GRID 148
#define GTHREADS 512

// ---------------- scratch (no allocations allowed) ----------------
__device__ int    g_deg[N_NODES];
__device__ float  g_invdeg[N_NODES];
__device__ int    g_off[N_NODES + 1];
__device__ int    g_cursor[N_NODES];
__device__ int    g_csr[N_EDGES];
__device__ float  g_h0[(size_t)N_NODES * D];
__device__ float  g_h1[(size_t)N_NODES * D];
__device__ float  g_hn[(size_t)N_NODES * D];
__device__ __align__(16) __half g_xf16[(size_t)N_NODES * D];
__device__ __align__(16) __half g_hf16a[(size_t)N_NODES * D];
__device__ __align__(16) __half g_hf16b[(size_t)N_NODES * D];

// ---------------- CSR build ----------------
__global__ void zero_deg_kernel() {
    int i = blockIdx.x * blockDim.x + threadIdx.x;
    if (i < N_NODES) g_deg[i] = 0;
}

__global__ void count_deg_kernel(const int* __restrict__ dst) {
    int e = blockIdx.x * blockDim.x + threadIdx.x;
    if (e < N_EDGES) atomicAdd(&g_deg[dst[e]], 1);
}

__global__ void scan_offsets_kernel() {
    __shared__ int warp_sums[32];
    __shared__ int carry_sh;
    int t = threadIdx.x, lane = t & 31, w = t >> 5;
    if (t == 0) carry_sh = 0;
    __syncthreads();
    for (int base = 0; base < N_NODES; base += 4096) {
        int i4 = base + t * 4;
        int4 v = make_int4(0, 0, 0, 0);
        if (i4 < N_NODES) v = *(const int4*)&g_deg[i4];
        int s0 = v.x, s1 = s0 + v.y, s2 = s1 + v.z, s3 = s2 + v.w;
        int incl = s3;
        #pragma unroll
        for (int off = 1; off < 32; off <<= 1) {
            int x = __shfl_up_sync(0xffffffffu, incl, off);
            if (lane >= off) incl += x;
        }
        if (lane == 31) warp_sums[w] = incl;
        __syncthreads();
        if (w == 0) {
            int s = warp_sums[lane];
            #pragma unroll
            for (int off = 1; off < 32; off <<= 1) {
                int x = __shfl_up_sync(0xffffffffu, s, off);
                if (lane >= off) s += x;
            }
            warp_sums[lane] = s;
        }
        __syncthreads();
        int carry = carry_sh;
        int woff = (w > 0) ? warp_sums[w - 1] : 0;
        int excl = carry + woff + incl - s3;
        if (i4 < N_NODES) {
            *(int4*)&g_off[i4] =
                make_int4(excl, excl + s0, excl + s1, excl + s2);
            *(float4*)&g_invdeg[i4] = make_float4(
                1.0f / (float)max(v.x, 1), 1.0f / (float)max(v.y, 1),
                1.0f / (float)max(v.z, 1), 1.0f / (float)max(v.w, 1));
            *(int4*)&g_cursor[i4] = make_int4(0, 0, 0, 0);
        }
        __syncthreads();
        if (t == 1023) carry_sh = carry + woff + incl;
        __syncthreads();
    }
    if (t == 0) g_off[N_NODES] = carry_sh;
}

__global__ void fill_csr_kernel(const int* __restrict__ src,
                                const int* __restrict__ dst) {
    int e = blockIdx.x * blockDim.x + threadIdx.x;
    if (e < N_EDGES) {
        int d = dst[e];
        int p = atomicAdd(&g_cursor[d], 1);
        g_csr[g_off[d] + p] = src[e];
    }
}

// ---------------- x -> fp16 copy (once) ----------------
__global__ void convert_x_kernel(const float* __restrict__ x) {
    int i = blockIdx.x * blockDim.x + threadIdx.x;
    if (i < N_NODES * D / 4) {
        float4 v = ((const float4*)x)[i];
        __half2* o = (__half2*)g_xf16;
        o[i * 2]     = __floats2half2_rn(v.x, v.y);
        o[i * 2 + 1] = __floats2half2_rn(v.z, v.w);
    }
}

// ---------------- aggregation: one warp per node, fp16 gather ----------------
__device__ __forceinline__ void acc_h4(float4& a, uint2 r) {
    __half2 p0 = *reinterpret_cast<__half2*>(&r.x);
    __half2 p1 = *reinterpret_cast<__half2*>(&r.y);
    float2 f0 = __half22float2(p0);
    float2 f1 = __half22float2(p1);
    a.x += f0.x; a.y += f0.y; a.z += f1.x; a.w += f1.y;
}

__global__ void __launch_bounds__(256) aggregate_f16_kernel(
    const __half* __restrict__ hin16)
{
    int gw = (blockIdx.x * blockDim.x + threadIdx.x) >> 5;
    int lane = threadIdx.x & 31;
    if (gw >= N_NODES) return;
    int s = g_off[gw], e = g_off[gw + 1];
    const uint2* H = (const uint2*)hin16;   // 4 halves per lane
    float4 a0 = make_float4(0.f, 0.f, 0.f, 0.f);
    float4 a1 = a0, a2 = a0, a3 = a0;
    int j = s;
    for (; j + 4 <= e; j += 4) {
        int u0 = __ldg(&g_csr[j]);
        int u1 = __ldg(&g_csr[j + 1]);
        int u2 = __ldg(&g_csr[j + 2]);
        int u3 = __ldg(&g_csr[j + 3]);
        uint2 r0 = __ldg(&H[(size_t)u0 * 32 + lane]);
        uint2 r1 = __ldg(&H[(size_t)u1 * 32 + lane]);
        uint2 r2 = __ldg(&H[(size_t)u2 * 32 + lane]);
        uint2 r3 = __ldg(&H[(size_t)u3 * 32 + lane]);
        acc_h4(a0, r0); acc_h4(a1, r1); acc_h4(a2, r2); acc_h4(a3, r3);
    }
    for (; j < e; j++) {
        int u = __ldg(&g_csr[j]);
        uint2 r = __ldg(&H[(size_t)u * 32 + lane]);
        acc_h4(a0, r);
    }
    float inv = g_invdeg[gw];
    float4 r;
    r.x = (a0.x + a1.x + a2.x + a3.x) * inv;
    r.y = (a0.y + a1.y + a2.y + a3.y) * inv;
    r.z = (a0.z + a1.z + a2.z + a3.z) * inv;
    r.w = (a0.w + a1.w + a2.w + a3.w) * inv;
    ((float4*)g_hn)[(size_t)gw * 32 + lane] = r;
}

// ---------------- persistent bf16-split tensor-core GEMM (16 warps) ----------
//   C = Ahi*Whi + Alo*Whi + Ahi*Wlo  (fp32 accum, m16n8k16 bf16 mma.sync)
// 512 threads: warpM = warp>>1 (0..7, 16 rows each), warpN = warp&1.
#define ABUF (2 * 128 * APAD)                      // bf16 units per buffer
#define GEMM_SMEM_BYTES ((2 * 128 * KPAD + 2 * ABUF) * 2)   // 188416 B

__device__ __forceinline__ void mma_bf16(float c[4], uint32_t a0, uint32_t a1,
                                         uint32_t a2, uint32_t a3,
                                         uint32_t b0, uint32_t b1) {
    asm volatile(
        "mma.sync.aligned.m16n8k16.row.col.f32.bf16.bf16.f32 "
        "{%0,%1,%2,%3}, {%4,%5,%6,%7}, {%8,%9}, {%0,%1,%2,%3};"
        : "+f"(c[0]), "+f"(c[1]), "+f"(c[2]), "+f"(c[3])
        : "r"(a0), "r"(a1), "r"(a2), "r"(a3), "r"(b0), "r"(b1));
}

__global__ void __launch_bounds__(GTHREADS, 1) sage_gemm_kernel(
    const float* __restrict__ hin, const float* __restrict__ hn,
    const float* __restrict__ Ws, const float* __restrict__ Wn,
    const float* __restrict__ bias, float* __restrict__ out,
    __half* __restrict__ out16)
{
    extern __shared__ __align__(16) __nv_bfloat16 smem[];
    __nv_bfloat16* sWhi = smem;                       // [128][KPAD]
    __nv_bfloat16* sWlo = sWhi + 128 * KPAD;
    __nv_bfloat16* sA   = sWlo + 128 * KPAD;          // 2 x (hi | lo)

    int tid = threadIdx.x;
    int lane = tid & 31, warp = tid >> 5;
    int warpN = warp & 1, warpM = warp >> 1;
    int g = lane >> 2, tig = lane & 3;

    // ---- in-kernel weight split: fp32 -> hi/lo bf16, permuted-K layout ----
    for (int idx = tid; idx < 128 * 256; idx += GTHREADS) {
        int n = idx & 127;              // coalesced over n
        int k = idx >> 7;
        float w = (k < 128) ? __ldg(&Ws[k * 128 + n])
                            : __ldg(&Wn[(k - 128) * 128 + n]);
        __nv_bfloat16 hi = __float2bfloat16(w);
        __nv_bfloat16 lo = __float2bfloat16(w - __bfloat162float(hi));
        int group = k >> 4, l = k & 15;
        int p = ((l & 7) >> 1) * 4 + (l & 1) + ((l >> 3) << 1);
        int off = n * KPAD + group * 16 + p;
        sWhi[off] = hi;
        sWlo[off] = lo;
    }

    // bias cached in registers
    float bx[8], by[8];
    #pragma unroll
    for (int nf = 0; nf < 8; nf++) {
        int col = warpN * 64 + nf * 8 + tig * 2;
        bx[nf] = __ldg(&bias[col]);
        by[nf] = __ldg(&bias[col + 1]);
    }

    const int ptab[4] = {0, 8, 2, 10};

    for (int tile = blockIdx.x; tile < GEMM_TILES; tile += gridDim.x) {
        int m0 = tile * 128;

        float acc[8][4];
        #pragma unroll
        for (int nf = 0; nf < 8; nf++)
            #pragma unroll
            for (int r = 0; r < 4; r++) acc[nf][r] = 0.f;

        // preload chunk 0 (hin cols 0..31): 1024 float4, 2 per thread
        float4 pref[2];
        #pragma unroll
        for (int i = 0; i < 2; i++) {
            int idx = tid + GTHREADS * i;
            int r = idx >> 3, c4 = idx & 7;
            int m = m0 + r;
            pref[i] = make_float4(0.f, 0.f, 0.f, 0.f);
            if (m < N_NODES)
                pref[i] = __ldg((const float4*)(hin + (size_t)m * D + c4 * 4));
        }

        #pragma unroll 1
        for (int kc = 0; kc < 8; kc++) {
            __nv_bfloat16* sAhi = sA + (kc & 1) * ABUF;
            __nv_bfloat16* sAlo = sAhi + 128 * APAD;

            // convert prefetched fp32 -> hi/lo bf16, permuted-K smem
            #pragma unroll
            for (int i = 0; i < 2; i++) {
                int idx = tid + GTHREADS * i;
                int r = idx >> 3, c4 = idx & 7;
                float4 v = pref[i];
                __nv_bfloat16 hx = __float2bfloat16(v.x);
                __nv_bfloat16 hy = __float2bfloat16(v.y);
                __nv_bfloat16 hz = __float2bfloat16(v.z);
                __nv_bfloat16 hw = __float2bfloat16(v.w);
                __nv_bfloat16 lx = __float2bfloat16(v.x - __bfloat162float(hx));
                __nv_bfloat16 ly = __float2bfloat16(v.y - __bfloat162float(hy));
                __nv_bfloat16 lz = __float2bfloat16(v.z - __bfloat162float(hz));
                __nv_bfloat16 lw = __float2bfloat16(v.w - __bfloat162float(hw));
                uint32_t hp0 = ((uint32_t)__bfloat16_as_ushort(hy) << 16) |
                               __bfloat16_as_ushort(hx);
                uint32_t hp1 = ((uint32_t)__bfloat16_as_ushort(hw) << 16) |
                               __bfloat16_as_ushort(hz);
                uint32_t lp0 = ((uint32_t)__bfloat16_as_ushort(ly) << 16) |
                               __bfloat16_as_ushort(lx);
                uint32_t lp1 = ((uint32_t)__bfloat16_as_ushort(lw) << 16) |
                               __bfloat16_as_ushort(lz);
                int group = c4 >> 2;
                int p0 = ptab[c4 & 3];
                int base = r * APAD + group * 16;
                uint32_t* AH = (uint32_t*)sAhi;
                uint32_t* AL = (uint32_t*)sAlo;
                AH[(base + p0) >> 1]     = hp0;
                AH[(base + p0 + 4) >> 1] = hp1;
                AL[(base + p0) >> 1]     = lp0;
                AL[(base + p0 + 4) >> 1] = lp1;
            }
            __syncthreads();   // first iteration also covers W staging

            // prefetch next chunk
            if (kc < 7) {
                int nkc = kc + 1;
                const float* srcp = (nkc < 4) ? hin : hn;
                int koff = (nkc & 3) * 32;
                #pragma unroll
                for (int i = 0; i < 2; i++) {
                    int idx = tid + GTHREADS * i;
                    int r = idx >> 3, c4 = idx & 7;
                    int m = m0 + r;
                    pref[i] = make_float4(0.f, 0.f, 0.f, 0.f);
                    if (m < N_NODES)
                        pref[i] = __ldg((const float4*)(srcp + (size_t)m * D +
                                                        koff + c4 * 4));
                }
            }

            // mma over current buffer
            #pragma unroll
            for (int ks = 0; ks < 2; ks++) {
                int ka = ks * 16;
                int kw = kc * 32 + ks * 16;
                int r0 = warpM * 16;
                uint2 t0 = *(const uint2*)&sAhi[(r0 + g) * APAD + ka + tig * 4];
                uint2 t1 = *(const uint2*)&sAhi[(r0 + g + 8) * APAD + ka + tig * 4];
                uint32_t Ah0 = t0.x, Ah1 = t1.x, Ah2 = t0.y, Ah3 = t1.y;
                uint2 u0 = *(const uint2*)&sAlo[(r0 + g) * APAD + ka + tig * 4];
                uint2 u1 = *(const uint2*)&sAlo[(r0 + g + 8) * APAD + ka + tig * 4];
                uint32_t Al0 = u0.x, Al1 = u1.x, Al2 = u0.y, Al3 = u1.y;
                #pragma unroll
                for (int nf = 0; nf < 8; nf++) {
                    int nr = warpN * 64 + nf * 8 + g;
                    uint2 bh = *(const uint2*)&sWhi[nr * KPAD + kw + tig * 4];
                    uint2 bl = *(const uint2*)&sWlo[nr * KPAD + kw + tig * 4];
                    mma_bf16(acc[nf], Ah0, Ah1, Ah2, Ah3, bh.x, bh.y);
                    mma_bf16(acc[nf], Al0, Al1, Al2, Al3, bh.x, bh.y);
                    mma_bf16(acc[nf], Ah0, Ah1, Ah2, Ah3, bl.x, bl.y);
                }
            }
        }

        // epilogue: + bias, relu, store fp32 + fp16 copy
        int row0 = m0 + warpM * 16 + g;
        #pragma unroll
        for (int nf = 0; nf < 8; nf++) {
            int col = warpN * 64 + nf * 8 + tig * 2;
            if (row0 < N_NODES) {
                float r0 = acc[nf][0] + bx[nf]; r0 = r0 > 0.f ? r0 : 0.f;
                float r1 = acc[nf][1] + by[nf]; r1 = r1 > 0.f ? r1 : 0.f;
                *(float2*)&out[(size_t)row0 * D + col] = make_float2(r0, r1);
                *(__half2*)&out16[(size_t)row0 * D + col] = __floats2half2_rn(r0, r1);
            }
            if (row0 + 8 < N_NODES) {
                float r2 = acc[nf][2] + bx[nf]; r2 = r2 > 0.f ? r2 : 0.f;
                float r3 = acc[nf][3] + by[nf]; r3 = r3 > 0.f ? r3 : 0.f;
                *(float2*)&out[(size_t)(row0 + 8) * D + col] = make_float2(r2, r3);
                *(__half2*)&out16[(size_t)(row0 + 8) * D + col] = __floats2half2_rn(r2, r3);
            }
        }
    }
}

// ---------------- launch ----------------
extern "C" void kernel_launch(void* const* d_in, const int* in_sizes, int n_in,
                              void* d_out, int out_size)
{
    const float* x       = (const float*)d_in[0];
    const float* W_self  = (const float*)d_in[1];
    const float* W_neigh = (const float*)d_in[2];
    const float* bias    = (const float*)d_in[3];
    const int*   src     = (const int*)d_in[4];
    const int*   dst     = (const int*)d_in[5];
    float* out = (float*)d_out;

    void *p0, *p1, *pn, *px16, *pa16, *pb16;
    cudaGetSymbolAddress(&p0, g_h0);
    cudaGetSymbolAddress(&p1, g_h1);
    cudaGetSymbolAddress(&pn, g_hn);
    cudaGetSymbolAddress(&px16, g_xf16);
    cudaGetSymbolAddress(&pa16, g_hf16a);
    cudaGetSymbolAddress(&pb16, g_hf16b);
    float* h0 = (float*)p0;
    float* h1 = (float*)p1;
    float* hn = (float*)pn;
    __half* x16 = (__half*)px16;
    __half* a16 = (__half*)pa16;
    __half* b16 = (__half*)pb16;

    cudaFuncSetAttribute(sage_gemm_kernel,
                         cudaFuncAttributeMaxDynamicSharedMemorySize,
                         GEMM_SMEM_BYTES);

    zero_deg_kernel<<<(N_NODES + 255) / 256, 256>>>();
    count_deg_kernel<<<(N_EDGES + 255) / 256, 256>>>(dst);
    scan_offsets_kernel<<<1, 1024>>>();
    fill_csr_kernel<<<(N_EDGES + 255) / 256, 256>>>(src, dst);
    convert_x_kernel<<<(N_NODES * D / 4 + 255) / 256, 256>>>(x);

    const float* hin32 = x;
    const __half* hin16 = x16;
    float* houts32[3] = {h0, h1, out};
    __half* houts16[3] = {a16, b16, a16};
    for (int l = 0; l < L_LAYERS; l++) {
        aggregate_f16_kernel<<<(N_NODES + 7) / 8, 256>>>(hin16);
        sage_gemm_kernel<<<GEMM_GRID, GTHREADS, GEMM_SMEM_BYTES>>>(
            hin32, hn, W_self + (size_t)l * D * D, W_neigh + (size_t)l * D * D,
            bias + (size_t)l * D, houts32[l], houts16[l]);
        hin32 = houts32[l];
        hin16 = houts16[l];
    }
}